// round 15
// baseline (speedup 1.0000x reference)
#include <cuda_runtime.h>
#include <cuda_fp16.h>
#include <cstdint>
#include <math.h>

#define NTOK 4096
#define DIM  1024
#define HID  4096
#define NEXP 8
#define MAXA (NTOK * 2)

// ---------------- device scratch (static, allocation-free) ----------------
__device__ int   g_cnt[NEXP];
__device__ int   g_list[NEXP][MAXA];
__device__ float g_wgt[MAXA];
__device__ __half g_x[(size_t)NTOK * DIM];
__device__ __half g_w1[(size_t)NEXP * DIM * HID];   // native [e][d][h]
__device__ __half g_w2[(size_t)NEXP * HID * DIM];   // native [e][h][d]
__device__ __half g_h[(size_t)MAXA * HID];

// ---------------- helpers ----------------
__device__ __forceinline__ uint32_t smem_u32(const void* p) {
    uint32_t a;
    asm("{ .reg .u64 t; cvta.to.shared.u64 t, %1; cvt.u32.u64 %0, t; }" : "=r"(a) : "l"(p));
    return a;
}
__device__ __forceinline__ void cp16(uint32_t dst, const void* src, uint32_t srcsz) {
    asm volatile("cp.async.cg.shared.global [%0], [%1], 16, %2;"
                 :: "r"(dst), "l"(src), "r"(srcsz) : "memory");
}
#define CP_COMMIT() asm volatile("cp.async.commit_group;" ::: "memory")
#define CP_WAIT(n)  asm volatile("cp.async.wait_group %0;" :: "n"(n) : "memory")

__device__ __forceinline__ void ldsm4(uint32_t* r, uint32_t addr) {
    asm volatile("ldmatrix.sync.aligned.m8n8.x4.shared.b16 {%0,%1,%2,%3}, [%4];"
                 : "=r"(r[0]), "=r"(r[1]), "=r"(r[2]), "=r"(r[3]) : "r"(addr));
}
__device__ __forceinline__ void ldsm4t(uint32_t* r, uint32_t addr) {
    asm volatile("ldmatrix.sync.aligned.m8n8.x4.trans.shared.b16 {%0,%1,%2,%3}, [%4];"
                 : "=r"(r[0]), "=r"(r[1]), "=r"(r[2]), "=r"(r[3]) : "r"(addr));
}
__device__ __forceinline__ void mma16816(float* c, const uint32_t* a, uint32_t b0, uint32_t b1) {
    asm volatile(
        "mma.sync.aligned.m16n8k16.row.col.f32.f16.f16.f32 "
        "{%0,%1,%2,%3}, {%4,%5,%6,%7}, {%8,%9}, {%0,%1,%2,%3};"
        : "+f"(c[0]), "+f"(c[1]), "+f"(c[2]), "+f"(c[3])
        : "r"(a[0]), "r"(a[1]), "r"(a[2]), "r"(a[3]), "r"(b0), "r"(b1));
}
__device__ __forceinline__ uint32_t pack_h2(float a, float b) {
    __half2 t = __floats2half2_rn(a, b);
    return *reinterpret_cast<uint32_t*>(&t);
}
#define SWZ(o) ((o) ^ (((o) >> 3) & 0x70))

// ---------------- tiny: reset expert counters ----------------
__global__ void reset_cnt() {
    if (threadIdx.x < NEXP) g_cnt[threadIdx.x] = 0;
}

// ================= fused prep kernel =================
// blocks [0,512)            : gating (8 tokens/block) + fused x->fp16
// blocks [512,16896)        : W1 fp32->fp16 streaming convert
// blocks [16896,33280)      : W2 fp32->fp16 streaming convert
// blocks [33280,37376)      : zero output
__global__ void __launch_bounds__(256)
prep_kernel(const float* __restrict__ x,  const float* __restrict__ Wg,
            const float* __restrict__ bg, const float* __restrict__ W1,
            const float* __restrict__ W2, float* __restrict__ out) {
    const int b = blockIdx.x;
    const int t = threadIdx.x;

    if (b < 512) {
        int tok  = b * 8 + (t >> 5);
        int lane = t & 31;
        const float* xr = x + (size_t)tok * DIM;
        __half* xo = g_x + (size_t)tok * DIM;
        float acc[NEXP];
#pragma unroll
        for (int e = 0; e < NEXP; e++) acc[e] = 0.f;
        for (int d = lane * 2; d < DIM; d += 64) {
            float2 xv = *reinterpret_cast<const float2*>(xr + d);
            *reinterpret_cast<uint32_t*>(xo + d) = pack_h2(xv.x, xv.y);
            const float* wr0 = Wg + d * NEXP;
#pragma unroll
            for (int e = 0; e < NEXP; e++) acc[e] += xv.x * wr0[e];
            const float* wr1 = Wg + (d + 1) * NEXP;
#pragma unroll
            for (int e = 0; e < NEXP; e++) acc[e] += xv.y * wr1[e];
        }
#pragma unroll
        for (int off = 16; off; off >>= 1)
#pragma unroll
            for (int e = 0; e < NEXP; e++)
                acc[e] += __shfl_xor_sync(0xffffffffu, acc[e], off);
        if (lane == 0) {
            float logit[NEXP], m = -1e30f;
#pragma unroll
            for (int e = 0; e < NEXP; e++) { logit[e] = acc[e] + bg[e]; m = fmaxf(m, logit[e]); }
            float p[NEXP], s = 0.f;
#pragma unroll
            for (int e = 0; e < NEXP; e++) { p[e] = expf(logit[e] - m); s += p[e]; }
            float inv = 1.f / s;
#pragma unroll
            for (int e = 0; e < NEXP; e++) p[e] *= inv;
            int e0 = 0;
#pragma unroll
            for (int e = 1; e < NEXP; e++) if (p[e] > p[e0]) e0 = e;
            int e1 = (e0 == 0) ? 1 : 0;
#pragma unroll
            for (int e = 0; e < NEXP; e++) if (e != e0 && p[e] > p[e1]) e1 = e;
            g_wgt[2 * tok + 0] = p[e0];
            g_wgt[2 * tok + 1] = p[e1];
            int p0 = atomicAdd(&g_cnt[e0], 1); g_list[e0][p0] = 2 * tok + 0;
            int p1 = atomicAdd(&g_cnt[e1], 1); g_list[e1][p1] = 2 * tok + 1;
        }
    } else if (b < 33280) {
        const bool isW1 = b < 16896;
        const float* src = isW1 ? W1 : W2;
        __half* dst = isW1 ? g_w1 : g_w2;
        size_t i = ((size_t)(b - (isW1 ? 512 : 16896)) * 256 + t) * 8;
        float v[8];
        *reinterpret_cast<float4*>(v)     = *reinterpret_cast<const float4*>(src + i);
        *reinterpret_cast<float4*>(v + 4) = *reinterpret_cast<const float4*>(src + i + 4);
        uint32_t p[4];
#pragma unroll
        for (int j = 0; j < 4; j++) p[j] = pack_h2(v[2 * j], v[2 * j + 1]);
        *reinterpret_cast<uint4*>(dst + i) = make_uint4(p[0], p[1], p[2], p[3]);
    } else {
        size_t i = ((size_t)(b - 33280) * 256 + t) * 4;
        *reinterpret_cast<float4*>(out + i) = make_float4(0.f, 0.f, 0.f, 0.f);
    }
}

// ------- phase1: 64x64 CTA, K-chunk 128, 32KB stages, 3 CTAs/SM (gemm2 clone) -------
__global__ void __launch_bounds__(256, 3)
moe_gemm1(const float* __restrict__ bias) {
    constexpr int KD  = DIM;    // 1024
    constexpr int ND  = HID;    // 4096
    constexpr int NCH = KD / 128;    // 8
    constexpr int STG = 32 * 1024;   // [A0 8K][A1 8K][B 16K]

    const __half* A = g_x;
    const __half* B = g_w1;

    const int e   = blockIdx.z;
    const int cnt = g_cnt[e];
    const int m0  = blockIdx.y * 64;
    if (m0 >= cnt) return;
    const int n0  = blockIdx.x * 64;
    const int tid = threadIdx.x;

    extern __shared__ char smraw[];
    char* tilep = (char*)(((uintptr_t)smraw + 1023) & ~(uintptr_t)1023);
    const uint32_t sbase = smem_u32(tilep);
    __shared__ float s_bias[64];
    if (tid < 64) s_bias[tid] = bias[(size_t)e * ND + n0 + tid];

    const int seg = tid & 7;
    const int rg  = tid >> 3;
    uint32_t aoff[2], avalid[2], swza[2];
#pragma unroll
    for (int p = 0; p < 2; p++) {
        int r   = rg + 32 * p;
        int idx = m0 + r;
        int a   = (idx < cnt) ? g_list[e][idx] : 0;
        avalid[p] = (idx < cnt) ? 16u : 0u;
        aoff[p]   = (uint32_t)(a >> 1) * KD + seg * 8;
        swza[p]   = SWZ(r * 128 + seg * 16);
    }
    uint32_t boff[4], swzb[4];
#pragma unroll
    for (int p = 0; p < 4; p++) {
        int kr  = rg + 32 * p;
        boff[p] = ((uint32_t)e * KD + kr) * ND + n0 + seg * 8;
        swzb[p] = SWZ(kr * 128 + seg * 16);
    }

    const int lane = tid & 31;
    const int wid  = tid >> 5;
    const int wm   = wid >> 1;
    const int wn   = wid & 1;
    uint32_t abase, axor;
    {
        int row = wm * 16 + (lane & 15);
        abase   = row * 128 + (lane >> 4) * 16;
        axor    = (row & 7) << 4;
    }
    uint32_t bfr[2];
#pragma unroll
    for (int p = 0; p < 2; p++)
        bfr[p] = (lane & 15) * 128 +
                 ((((uint32_t)(4 * wn + 2 * p + (lane >> 4))) * 16) ^ ((lane & 7) << 4));

    float acc[4][4];
#pragma unroll
    for (int j = 0; j < 4; j++)
#pragma unroll
        for (int q = 0; q < 4; q++) acc[j][q] = 0.f;

#define ISSUE_CHUNK1(CC, BUF) do {                                             \
        const uint32_t _koA = (uint32_t)(CC) * 128;                            \
        const uint32_t _koB = (uint32_t)(CC) * 128 * ND;                       \
        uint32_t _sb = sbase + (BUF) * STG;                                    \
        _Pragma("unroll")                                                      \
        for (int s = 0; s < 2; s++)                                            \
            _Pragma("unroll")                                                  \
            for (int p = 0; p < 2; p++)                                        \
                cp16(_sb + s * 8192 + swza[p],                                 \
                     A + aoff[p] + _koA + s * 64, avalid[p]);                  \
        _Pragma("unroll")                                                      \
        for (int p = 0; p < 4; p++)                                            \
            cp16(_sb + 16384 + swzb[p], B + boff[p] + _koB, 16u);              \
        CP_COMMIT();                                                           \
    } while (0)

    ISSUE_CHUNK1(0, 0);

    for (int c = 0; c < NCH; ++c) {
        if (c + 1 < NCH) {
            ISSUE_CHUNK1(c + 1, (c + 1) & 1);
            CP_WAIT(1);
        } else {
            CP_WAIT(0);
        }
        __syncthreads();

        const uint32_t sb = sbase + (c & 1) * STG;
        const uint32_t bb_base = sb + 16384;
#pragma unroll
        for (int kk = 0; kk < 8; kk++) {
            const uint32_t subA = (kk >> 2) * 8192;
            const uint32_t k4   = (kk & 3) * 32;
            uint32_t ah[4], bb[2][4];
            ldsm4(ah, sb + subA + ((abase + k4) ^ axor));
#pragma unroll
            for (int p = 0; p < 2; p++)
                ldsm4t(bb[p], bb_base + kk * 2048 + bfr[p]);
#pragma unroll
            for (int p = 0; p < 2; p++) {
                mma16816(acc[2 * p],     ah, bb[p][0], bb[p][1]);
                mma16816(acc[2 * p + 1], ah, bb[p][2], bb[p][3]);
            }
        }
        __syncthreads();
    }
#undef ISSUE_CHUNK1

    const int quad  = lane >> 2;
    const int qid   = lane & 3;
    const int ncol0 = wn * 32;

#pragma unroll
    for (int rv = 0; rv < 2; rv++) {
        int midx = m0 + wm * 16 + rv * 8 + quad;
        if (midx >= cnt) continue;
        int a = g_list[e][midx];
        __half* dh = g_h + (size_t)a * HID + n0;
#pragma unroll
        for (int nf = 0; nf < 4; nf++) {
            int nloc = ncol0 + nf * 8 + 2 * qid;
            float v0 = fmaxf(acc[nf][2 * rv]     + s_bias[nloc],     0.f);
            float v1 = fmaxf(acc[nf][2 * rv + 1] + s_bias[nloc + 1], 0.f);
            *reinterpret_cast<uint32_t*>(dh + nloc) = pack_h2(v0, v1);
        }
    }
}

// ---------------- phase2: 64x64 CTA, warps 4m x 2n; 3 CTAs/SM ----------------
__global__ void __launch_bounds__(256, 3)
moe_gemm2(const float* __restrict__ bias, float* __restrict__ out) {
    constexpr int KD  = HID;    // 4096
    constexpr int ND  = DIM;    // 1024
    constexpr int NCH = KD / 128;
    constexpr int STG = 32 * 1024;

    const __half* A = g_h;
    const __half* B = g_w2;

    const int e   = blockIdx.z;
    const int cnt = g_cnt[e];
    const int m0  = blockIdx.y * 64;
    if (m0 >= cnt) return;
    const int n0  = blockIdx.x * 64;
    const int tid = threadIdx.x;

    extern __shared__ char smraw[];
    char* tilep = (char*)(((uintptr_t)smraw + 1023) & ~(uintptr_t)1023);
    const uint32_t sbase = smem_u32(tilep);
    __shared__ float s_bias[64];
    if (tid < 64) s_bias[tid] = bias[(size_t)e * ND + n0 + tid];

    const int seg = tid & 7;
    const int rg  = tid >> 3;
    uint32_t aoff[2], avalid[2], swza[2];
#pragma unroll
    for (int p = 0; p < 2; p++) {
        int r   = rg + 32 * p;
        int idx = m0 + r;
        int a   = (idx < cnt) ? g_list[e][idx] : 0;
        avalid[p] = (idx < cnt) ? 16u : 0u;
        aoff[p]   = (uint32_t)a * KD + seg * 8;
        swza[p]   = SWZ(r * 128 + seg * 16);
    }
    uint32_t boff[4], swzb[4];
#pragma unroll
    for (int p = 0; p < 4; p++) {
        int kr  = rg + 32 * p;
        boff[p] = ((uint32_t)e * KD + kr) * ND + n0 + seg * 8;
        swzb[p] = SWZ(kr * 128 + seg * 16);
    }

    const int lane = tid & 31;
    const int wid  = tid >> 5;
    const int wm   = wid >> 1;
    const int wn   = wid & 1;
    uint32_t abase, axor;
    {
        int row = wm * 16 + (lane & 15);
        abase   = row * 128 + (lane >> 4) * 16;
        axor    = (row & 7) << 4;
    }
    uint32_t bfr[2];
#pragma unroll
    for (int p = 0; p < 2; p++)
        bfr[p] = (lane & 15) * 128 +
                 ((((uint32_t)(4 * wn + 2 * p + (lane >> 4))) * 16) ^ ((lane & 7) << 4));

    float acc[4][4];
#pragma unroll
    for (int j = 0; j < 4; j++)
#pragma unroll
        for (int q = 0; q < 4; q++) acc[j][q] = 0.f;

#define ISSUE_CHUNK2(CC, BUF) do {                                             \
        const uint32_t _koA = (uint32_t)(CC) * 128;                            \
        const uint32_t _koB = (uint32_t)(CC) * 128 * ND;                       \
        uint32_t _sb = sbase + (BUF) * STG;                                    \
        _Pragma("unroll")                                                      \
        for (int s = 0; s < 2; s++)                                            \
            _Pragma("unroll")                                                  \
            for (int p = 0; p < 2; p++)                                        \
                cp16(_sb + s * 8192 + swza[p],                                 \
                     A + aoff[p] + _koA + s * 64, avalid[p]);                  \
        _Pragma("unroll")                                                      \
        for (int p = 0; p < 4; p++)                                            \
            cp16(_sb + 16384 + swzb[p], B + boff[p] + _koB, 16u);              \
        CP_COMMIT();                                                           \
    } while (0)

    ISSUE_CHUNK2(0, 0);

    for (int c = 0; c < NCH; ++c) {
        if (c + 1 < NCH) {
            ISSUE_CHUNK2(c + 1, (c + 1) & 1);
            CP_WAIT(1);
        } else {
            CP_WAIT(0);
        }
        __syncthreads();

        const uint32_t sb = sbase + (c & 1) * STG;
        const uint32_t bb_base = sb + 16384;
#pragma unroll
        for (int kk = 0; kk < 8; kk++) {
            const uint32_t subA = (kk >> 2) * 8192;
            const uint32_t k4   = (kk & 3) * 32;
            uint32_t ah[4], bb[2][4];
            ldsm4(ah, sb + subA + ((abase + k4) ^ axor));
#pragma unroll
            for (int p = 0; p < 2; p++)
                ldsm4t(bb[p], bb_base + kk * 2048 + bfr[p]);
#pragma unroll
            for (int p = 0; p < 2; p++) {
                mma16816(acc[2 * p],     ah, bb[p][0], bb[p][1]);
                mma16816(acc[2 * p + 1], ah, bb[p][2], bb[p][3]);
            }
        }
        __syncthreads();
    }
#undef ISSUE_CHUNK2

    const int quad  = lane >> 2;
    const int qid   = lane & 3;
    const int ncol0 = wn * 32;

#pragma unroll
    for (int rv = 0; rv < 2; rv++) {
        int midx = m0 + wm * 16 + rv * 8 + quad;
        if (midx >= cnt) continue;
        int a = g_list[e][midx];
        float w = g_wgt[a];
        float* op = out + (size_t)(a >> 1) * DIM + n0;
#pragma unroll
        for (int nf = 0; nf < 4; nf++) {
            int nloc = ncol0 + nf * 8 + 2 * qid;
            atomicAdd(op + nloc,     (acc[nf][2 * rv]     + s_bias[nloc])     * w);
            atomicAdd(op + nloc + 1, (acc[nf][2 * rv + 1] + s_bias[nloc + 1]) * w);
        }
    }
}

// ---------------- launch (sequential) ----------------
extern "C" void kernel_launch(void* const* d_in, const int* in_sizes, int n_in,
                              void* d_out, int out_size) {
    const float* x  = (const float*)d_in[0];
    const float* Wg = (const float*)d_in[1];
    const float* bg = (const float*)d_in[2];
    const float* W1 = (const float*)d_in[3];
    const float* b1 = (const float*)d_in[4];
    const float* W2 = (const float*)d_in[5];
    const float* b2 = (const float*)d_in[6];
    float* out = (float*)d_out;

    const int SMEM1 = 2 * 32 * 1024 + 1024;
    const int SMEM2 = 2 * 32 * 1024 + 1024;
    cudaFuncSetAttribute((const void*)moe_gemm1,
                         cudaFuncAttributeMaxDynamicSharedMemorySize, SMEM1);
    cudaFuncSetAttribute((const void*)moe_gemm2,
                         cudaFuncAttributeMaxDynamicSharedMemorySize, SMEM2);

    reset_cnt<<<1, 32>>>();
    prep_kernel<<<37376, 256>>>(x, Wg, bg, W1, W2, out);
    moe_gemm1<<<dim3(HID / 64, MAXA / 64, NEXP), 256, SMEM1>>>(b1);
    moe_gemm2<<<dim3(DIM / 64, MAXA / 64, NEXP), 256, SMEM2>>>(b2, out);
}

// round 16
// speedup vs baseline: 1.0760x; 1.0760x over previous
#include <cuda_runtime.h>
#include <cuda_fp16.h>
#include <cstdint>
#include <math.h>

#define NTOK 4096
#define DIM  1024
#define HID  4096
#define NEXP 8
#define MAXA (NTOK * 2)

// ---------------- device scratch (static, allocation-free) ----------------
__device__ int   g_cnt[NEXP];
__device__ int   g_list[NEXP][MAXA];
__device__ float g_wgt[MAXA];
__device__ __half g_x[(size_t)NTOK * DIM];
__device__ __half g_w1[(size_t)NEXP * DIM * HID];   // native [e][d][h]
__device__ __half g_w2[(size_t)NEXP * HID * DIM];   // native [e][h][d]
__device__ __half g_h[(size_t)MAXA * HID];

// ---------------- helpers ----------------
__device__ __forceinline__ uint32_t smem_u32(const void* p) {
    uint32_t a;
    asm("{ .reg .u64 t; cvta.to.shared.u64 t, %1; cvt.u32.u64 %0, t; }" : "=r"(a) : "l"(p));
    return a;
}
__device__ __forceinline__ void cp16(uint32_t dst, const void* src, uint32_t srcsz) {
    asm volatile("cp.async.cg.shared.global [%0], [%1], 16, %2;"
                 :: "r"(dst), "l"(src), "r"(srcsz) : "memory");
}
#define CP_COMMIT() asm volatile("cp.async.commit_group;" ::: "memory")
#define CP_WAIT(n)  asm volatile("cp.async.wait_group %0;" :: "n"(n) : "memory")

__device__ __forceinline__ void ldsm4(uint32_t* r, uint32_t addr) {
    asm volatile("ldmatrix.sync.aligned.m8n8.x4.shared.b16 {%0,%1,%2,%3}, [%4];"
                 : "=r"(r[0]), "=r"(r[1]), "=r"(r[2]), "=r"(r[3]) : "r"(addr));
}
__device__ __forceinline__ void ldsm4t(uint32_t* r, uint32_t addr) {
    asm volatile("ldmatrix.sync.aligned.m8n8.x4.trans.shared.b16 {%0,%1,%2,%3}, [%4];"
                 : "=r"(r[0]), "=r"(r[1]), "=r"(r[2]), "=r"(r[3]) : "r"(addr));
}
__device__ __forceinline__ void mma16816(float* c, const uint32_t* a, uint32_t b0, uint32_t b1) {
    asm volatile(
        "mma.sync.aligned.m16n8k16.row.col.f32.f16.f16.f32 "
        "{%0,%1,%2,%3}, {%4,%5,%6,%7}, {%8,%9}, {%0,%1,%2,%3};"
        : "+f"(c[0]), "+f"(c[1]), "+f"(c[2]), "+f"(c[3])
        : "r"(a[0]), "r"(a[1]), "r"(a[2]), "r"(a[3]), "r"(b0), "r"(b1));
}
__device__ __forceinline__ uint32_t pack_h2(float a, float b) {
    __half2 t = __floats2half2_rn(a, b);
    return *reinterpret_cast<uint32_t*>(&t);
}
#define SWZ(o) ((o) ^ (((o) >> 3) & 0x70))

// ---------------- tiny: reset expert counters ----------------
__global__ void reset_cnt() {
    if (threadIdx.x < NEXP) g_cnt[threadIdx.x] = 0;
}

// ================= fused prep kernel =================
// blocks [0,512)            : gating (8 tokens/block) + fused x->fp16
// blocks [512,16896)        : W1 fp32->fp16 streaming convert
// blocks [16896,33280)      : W2 fp32->fp16 streaming convert
// blocks [33280,37376)      : zero output
__global__ void __launch_bounds__(256)
prep_kernel(const float* __restrict__ x,  const float* __restrict__ Wg,
            const float* __restrict__ bg, const float* __restrict__ W1,
            const float* __restrict__ W2, float* __restrict__ out) {
    const int b = blockIdx.x;
    const int t = threadIdx.x;

    if (b < 512) {
        int tok  = b * 8 + (t >> 5);
        int lane = t & 31;
        const float* xr = x + (size_t)tok * DIM;
        __half* xo = g_x + (size_t)tok * DIM;
        float acc[NEXP];
#pragma unroll
        for (int e = 0; e < NEXP; e++) acc[e] = 0.f;
        for (int d = lane * 2; d < DIM; d += 64) {
            float2 xv = *reinterpret_cast<const float2*>(xr + d);
            *reinterpret_cast<uint32_t*>(xo + d) = pack_h2(xv.x, xv.y);
            const float* wr0 = Wg + d * NEXP;
#pragma unroll
            for (int e = 0; e < NEXP; e++) acc[e] += xv.x * wr0[e];
            const float* wr1 = Wg + (d + 1) * NEXP;
#pragma unroll
            for (int e = 0; e < NEXP; e++) acc[e] += xv.y * wr1[e];
        }
#pragma unroll
        for (int off = 16; off; off >>= 1)
#pragma unroll
            for (int e = 0; e < NEXP; e++)
                acc[e] += __shfl_xor_sync(0xffffffffu, acc[e], off);
        if (lane == 0) {
            float logit[NEXP], m = -1e30f;
#pragma unroll
            for (int e = 0; e < NEXP; e++) { logit[e] = acc[e] + bg[e]; m = fmaxf(m, logit[e]); }
            float p[NEXP], s = 0.f;
#pragma unroll
            for (int e = 0; e < NEXP; e++) { p[e] = expf(logit[e] - m); s += p[e]; }
            float inv = 1.f / s;
#pragma unroll
            for (int e = 0; e < NEXP; e++) p[e] *= inv;
            int e0 = 0;
#pragma unroll
            for (int e = 1; e < NEXP; e++) if (p[e] > p[e0]) e0 = e;
            int e1 = (e0 == 0) ? 1 : 0;
#pragma unroll
            for (int e = 0; e < NEXP; e++) if (e != e0 && p[e] > p[e1]) e1 = e;
            g_wgt[2 * tok + 0] = p[e0];
            g_wgt[2 * tok + 1] = p[e1];
            int p0 = atomicAdd(&g_cnt[e0], 1); g_list[e0][p0] = 2 * tok + 0;
            int p1 = atomicAdd(&g_cnt[e1], 1); g_list[e1][p1] = 2 * tok + 1;
        }
    } else if (b < 33280) {
        const bool isW1 = b < 16896;
        const float* src = isW1 ? W1 : W2;
        __half* dst = isW1 ? g_w1 : g_w2;
        size_t i = ((size_t)(b - (isW1 ? 512 : 16896)) * 256 + t) * 8;
        float v[8];
        *reinterpret_cast<float4*>(v)     = *reinterpret_cast<const float4*>(src + i);
        *reinterpret_cast<float4*>(v + 4) = *reinterpret_cast<const float4*>(src + i + 4);
        uint32_t p[4];
#pragma unroll
        for (int j = 0; j < 4; j++) p[j] = pack_h2(v[2 * j], v[2 * j + 1]);
        *reinterpret_cast<uint4*>(dst + i) = make_uint4(p[0], p[1], p[2], p[3]);
    } else {
        size_t i = ((size_t)(b - 33280) * 256 + t) * 4;
        *reinterpret_cast<float4*>(out + i) = make_float4(0.f, 0.f, 0.f, 0.f);
    }
}

// ------- phase1: 128x128 CTA, K-chunk 128, 64KB stages, 2 CTAs/SM (R12) -------
__global__ void __launch_bounds__(256, 2)
moe_gemm1(const float* __restrict__ bias) {
    constexpr int KD  = DIM;    // 1024
    constexpr int ND  = HID;    // 4096
    constexpr int NCH = KD / 128;
    constexpr int STG = 64 * 1024;

    const __half* A = g_x;
    const __half* B = g_w1;

    const int e   = blockIdx.z;
    const int cnt = g_cnt[e];
    const int m0  = blockIdx.y * 128;
    if (m0 >= cnt) return;
    const int n0  = blockIdx.x * 128;
    const int tid = threadIdx.x;

    extern __shared__ char smraw[];
    char* tilep = (char*)(((uintptr_t)smraw + 1023) & ~(uintptr_t)1023);
    const uint32_t sbase = smem_u32(tilep);
    __shared__ float s_bias[128];
    if (tid < 128) s_bias[tid] = bias[(size_t)e * ND + n0 + tid];

    const int seg = tid & 7;
    const int rg  = tid >> 3;
    uint32_t aoff[4], avalid[4], swza[4];
#pragma unroll
    for (int p = 0; p < 4; p++) {
        int r   = rg + 32 * p;
        int idx = m0 + r;
        int a   = (idx < cnt) ? g_list[e][idx] : 0;
        avalid[p] = (idx < cnt) ? 16u : 0u;
        aoff[p]   = (uint32_t)(a >> 1) * KD + seg * 8;
        swza[p]   = SWZ(r * 128 + seg * 16);
    }
    const int bs  = tid & 15;
    const int brg = tid >> 4;
    uint32_t boff[8], swzb[8];
#pragma unroll
    for (int p = 0; p < 8; p++) {
        int kr  = brg + 16 * p;
        boff[p] = ((uint32_t)e * KD + kr) * ND + n0 + bs * 8;
        swzb[p] = (bs >> 3) * 16384 + SWZ(kr * 128 + (bs & 7) * 16);
    }

    const int lane = tid & 31;
    const int wid  = tid >> 5;
    const int wm   = wid >> 1;
    const int wn   = wid & 1;
    uint32_t abase[2], axor[2];
#pragma unroll
    for (int mf = 0; mf < 2; mf++) {
        int row   = wm * 32 + mf * 16 + (lane & 15);
        abase[mf] = row * 128 + (lane >> 4) * 16;
        axor[mf]  = (row & 7) << 4;
    }
    uint32_t bfr[4];
#pragma unroll
    for (int p = 0; p < 4; p++)
        bfr[p] = (lane & 15) * 128 +
                 ((((uint32_t)(2 * p + (lane >> 4))) * 16) ^ ((lane & 7) << 4));
    const uint32_t bhalf = wn * 16384;

    float acc[2][8][4];
#pragma unroll
    for (int i = 0; i < 2; i++)
#pragma unroll
        for (int j = 0; j < 8; j++)
#pragma unroll
            for (int q = 0; q < 4; q++) acc[i][j][q] = 0.f;

#define ISSUE_CHUNK1(CC, BUF) do {                                             \
        const uint32_t _koA = (uint32_t)(CC) * 128;                            \
        const uint32_t _koB = (uint32_t)(CC) * 128 * ND;                       \
        uint32_t _sb = sbase + (BUF) * STG;                                    \
        _Pragma("unroll")                                                      \
        for (int s = 0; s < 2; s++)                                            \
            _Pragma("unroll")                                                  \
            for (int p = 0; p < 4; p++)                                        \
                cp16(_sb + s * 16384 + swza[p],                                \
                     A + aoff[p] + _koA + s * 64, avalid[p]);                  \
        _Pragma("unroll")                                                      \
        for (int p = 0; p < 8; p++)                                            \
            cp16(_sb + 32768 + swzb[p], B + boff[p] + _koB, 16u);              \
        CP_COMMIT();                                                           \
    } while (0)

    ISSUE_CHUNK1(0, 0);

    for (int c = 0; c < NCH; ++c) {
        if (c + 1 < NCH) {
            ISSUE_CHUNK1(c + 1, (c + 1) & 1);
            CP_WAIT(1);
        } else {
            CP_WAIT(0);
        }
        __syncthreads();

        const uint32_t sb = sbase + (c & 1) * STG;
        const uint32_t bb_base = sb + 32768 + bhalf;
#pragma unroll
        for (int kk = 0; kk < 8; kk++) {
            const uint32_t subA = (kk >> 2) * 16384;
            const uint32_t k4   = (kk & 3) * 32;
            uint32_t ah[2][4], bb[4][4];
#pragma unroll
            for (int mf = 0; mf < 2; mf++)
                ldsm4(ah[mf], sb + subA + ((abase[mf] + k4) ^ axor[mf]));
#pragma unroll
            for (int p = 0; p < 4; p++)
                ldsm4t(bb[p], bb_base + kk * 2048 + bfr[p]);
#pragma unroll
            for (int mf = 0; mf < 2; mf++)
#pragma unroll
                for (int p = 0; p < 4; p++) {
                    mma16816(acc[mf][2 * p],     ah[mf], bb[p][0], bb[p][1]);
                    mma16816(acc[mf][2 * p + 1], ah[mf], bb[p][2], bb[p][3]);
                }
        }
        __syncthreads();
    }
#undef ISSUE_CHUNK1

    const int quad  = lane >> 2;
    const int qid   = lane & 3;
    const int ncol0 = wn * 64;

#pragma unroll
    for (int mf = 0; mf < 2; mf++) {
#pragma unroll
        for (int rv = 0; rv < 2; rv++) {
            int midx = m0 + wm * 32 + mf * 16 + rv * 8 + quad;
            if (midx >= cnt) continue;
            int a = g_list[e][midx];
            __half* dh = g_h + (size_t)a * HID + n0;
#pragma unroll
            for (int nf = 0; nf < 8; nf++) {
                int nloc = ncol0 + nf * 8 + 2 * qid;
                float v0 = fmaxf(acc[mf][nf][2 * rv]     + s_bias[nloc],     0.f);
                float v1 = fmaxf(acc[mf][nf][2 * rv + 1] + s_bias[nloc + 1], 0.f);
                *reinterpret_cast<uint32_t*>(dh + nloc) = pack_h2(v0, v1);
            }
        }
    }
}

// ---------------- phase2: 64x64 CTA, warps 4m x 2n; 3 CTAs/SM (R12) ----------------
__global__ void __launch_bounds__(256, 3)
moe_gemm2(const float* __restrict__ bias, float* __restrict__ out) {
    constexpr int KD  = HID;    // 4096
    constexpr int ND  = DIM;    // 1024
    constexpr int NCH = KD / 128;
    constexpr int STG = 32 * 1024;

    const __half* A = g_h;
    const __half* B = g_w2;

    const int e   = blockIdx.z;
    const int cnt = g_cnt[e];
    const int m0  = blockIdx.y * 64;
    if (m0 >= cnt) return;
    const int n0  = blockIdx.x * 64;
    const int tid = threadIdx.x;

    extern __shared__ char smraw[];
    char* tilep = (char*)(((uintptr_t)smraw + 1023) & ~(uintptr_t)1023);
    const uint32_t sbase = smem_u32(tilep);
    __shared__ float s_bias[64];
    if (tid < 64) s_bias[tid] = bias[(size_t)e * ND + n0 + tid];

    const int seg = tid & 7;
    const int rg  = tid >> 3;
    uint32_t aoff[2], avalid[2], swza[2];
#pragma unroll
    for (int p = 0; p < 2; p++) {
        int r   = rg + 32 * p;
        int idx = m0 + r;
        int a   = (idx < cnt) ? g_list[e][idx] : 0;
        avalid[p] = (idx < cnt) ? 16u : 0u;
        aoff[p]   = (uint32_t)a * KD + seg * 8;
        swza[p]   = SWZ(r * 128 + seg * 16);
    }
    uint32_t boff[4], swzb[4];
#pragma unroll
    for (int p = 0; p < 4; p++) {
        int kr  = rg + 32 * p;
        boff[p] = ((uint32_t)e * KD + kr) * ND + n0 + seg * 8;
        swzb[p] = SWZ(kr * 128 + seg * 16);
    }

    const int lane = tid & 31;
    const int wid  = tid >> 5;
    const int wm   = wid >> 1;
    const int wn   = wid & 1;
    uint32_t abase, axor;
    {
        int row = wm * 16 + (lane & 15);
        abase   = row * 128 + (lane >> 4) * 16;
        axor    = (row & 7) << 4;
    }
    uint32_t bfr[2];
#pragma unroll
    for (int p = 0; p < 2; p++)
        bfr[p] = (lane & 15) * 128 +
                 ((((uint32_t)(4 * wn + 2 * p + (lane >> 4))) * 16) ^ ((lane & 7) << 4));

    float acc[4][4];
#pragma unroll
    for (int j = 0; j < 4; j++)
#pragma unroll
        for (int q = 0; q < 4; q++) acc[j][q] = 0.f;

#define ISSUE_CHUNK2(CC, BUF) do {                                             \
        const uint32_t _koA = (uint32_t)(CC) * 128;                            \
        const uint32_t _koB = (uint32_t)(CC) * 128 * ND;                       \
        uint32_t _sb = sbase + (BUF) * STG;                                    \
        _Pragma("unroll")                                                      \
        for (int s = 0; s < 2; s++)                                            \
            _Pragma("unroll")                                                  \
            for (int p = 0; p < 2; p++)                                        \
                cp16(_sb + s * 8192 + swza[p],                                 \
                     A + aoff[p] + _koA + s * 64, avalid[p]);                  \
        _Pragma("unroll")                                                      \
        for (int p = 0; p < 4; p++)                                            \
            cp16(_sb + 16384 + swzb[p], B + boff[p] + _koB, 16u);              \
        CP_COMMIT();                                                           \
    } while (0)

    ISSUE_CHUNK2(0, 0);

    for (int c = 0; c < NCH; ++c) {
        if (c + 1 < NCH) {
            ISSUE_CHUNK2(c + 1, (c + 1) & 1);
            CP_WAIT(1);
        } else {
            CP_WAIT(0);
        }
        __syncthreads();

        const uint32_t sb = sbase + (c & 1) * STG;
        const uint32_t bb_base = sb + 16384;
#pragma unroll
        for (int kk = 0; kk < 8; kk++) {
            const uint32_t subA = (kk >> 2) * 8192;
            const uint32_t k4   = (kk & 3) * 32;
            uint32_t ah[4], bb[2][4];
            ldsm4(ah, sb + subA + ((abase + k4) ^ axor));
#pragma unroll
            for (int p = 0; p < 2; p++)
                ldsm4t(bb[p], bb_base + kk * 2048 + bfr[p]);
#pragma unroll
            for (int p = 0; p < 2; p++) {
                mma16816(acc[2 * p],     ah, bb[p][0], bb[p][1]);
                mma16816(acc[2 * p + 1], ah, bb[p][2], bb[p][3]);
            }
        }
        __syncthreads();
    }
#undef ISSUE_CHUNK2

    const int quad  = lane >> 2;
    const int qid   = lane & 3;
    const int ncol0 = wn * 32;

#pragma unroll
    for (int rv = 0; rv < 2; rv++) {
        int midx = m0 + wm * 16 + rv * 8 + quad;
        if (midx >= cnt) continue;
        int a = g_list[e][midx];
        float w = g_wgt[a];
        float* op = out + (size_t)(a >> 1) * DIM + n0;
#pragma unroll
        for (int nf = 0; nf < 4; nf++) {
            int nloc = ncol0 + nf * 8 + 2 * qid;
            atomicAdd(op + nloc,     (acc[nf][2 * rv]     + s_bias[nloc])     * w);
            atomicAdd(op + nloc + 1, (acc[nf][2 * rv + 1] + s_bias[nloc + 1]) * w);
        }
    }
}

// ---------------- launch (sequential) ----------------
extern "C" void kernel_launch(void* const* d_in, const int* in_sizes, int n_in,
                              void* d_out, int out_size) {
    const float* x  = (const float*)d_in[0];
    const float* Wg = (const float*)d_in[1];
    const float* bg = (const float*)d_in[2];
    const float* W1 = (const float*)d_in[3];
    const float* b1 = (const float*)d_in[4];
    const float* W2 = (const float*)d_in[5];
    const float* b2 = (const float*)d_in[6];
    float* out = (float*)d_out;

    const int SMEM1 = 2 * 64 * 1024 + 1024;
    const int SMEM2 = 2 * 32 * 1024 + 1024;
    cudaFuncSetAttribute((const void*)moe_gemm1,
                         cudaFuncAttributeMaxDynamicSharedMemorySize, SMEM1);
    cudaFuncSetAttribute((const void*)moe_gemm2,
                         cudaFuncAttributeMaxDynamicSharedMemorySize, SMEM2);

    reset_cnt<<<1, 32>>>();
    prep_kernel<<<37376, 256>>>(x, Wg, bg, W1, W2, out);
    moe_gemm1<<<dim3(HID / 128, MAXA / 128, NEXP), 256, SMEM1>>>(b1);
    moe_gemm2<<<dim3(DIM / 64, MAXA / 64, NEXP), 256, SMEM2>>>(b2, out);
}

// round 17
// speedup vs baseline: 1.1251x; 1.0456x over previous
#include <cuda_runtime.h>
#include <cuda_fp16.h>
#include <cstdint>
#include <math.h>

#define NTOK 4096
#define DIM  1024
#define HID  4096
#define NEXP 8
#define MAXA (NTOK * 2)

// ---------------- device scratch (static, allocation-free) ----------------
__device__ int   g_cnt[NEXP];
__device__ int   g_list[NEXP][MAXA];
__device__ float g_wgt[MAXA];
__device__ __half g_x[(size_t)NTOK * DIM];
__device__ __half g_w1[(size_t)NEXP * DIM * HID];   // native [e][d][h]
__device__ __half g_w2[(size_t)NEXP * HID * DIM];   // native [e][h][d]
__device__ __half g_h[(size_t)MAXA * HID];

// ---------------- helpers ----------------
__device__ __forceinline__ uint32_t smem_u32(const void* p) {
    uint32_t a;
    asm("{ .reg .u64 t; cvta.to.shared.u64 t, %1; cvt.u32.u64 %0, t; }" : "=r"(a) : "l"(p));
    return a;
}
__device__ __forceinline__ void cp16(uint32_t dst, const void* src, uint32_t srcsz) {
    asm volatile("cp.async.cg.shared.global [%0], [%1], 16, %2;"
                 :: "r"(dst), "l"(src), "r"(srcsz) : "memory");
}
#define CP_COMMIT() asm volatile("cp.async.commit_group;" ::: "memory")
#define CP_WAIT(n)  asm volatile("cp.async.wait_group %0;" :: "n"(n) : "memory")

__device__ __forceinline__ void ldsm4(uint32_t* r, uint32_t addr) {
    asm volatile("ldmatrix.sync.aligned.m8n8.x4.shared.b16 {%0,%1,%2,%3}, [%4];"
                 : "=r"(r[0]), "=r"(r[1]), "=r"(r[2]), "=r"(r[3]) : "r"(addr));
}
__device__ __forceinline__ void ldsm4t(uint32_t* r, uint32_t addr) {
    asm volatile("ldmatrix.sync.aligned.m8n8.x4.trans.shared.b16 {%0,%1,%2,%3}, [%4];"
                 : "=r"(r[0]), "=r"(r[1]), "=r"(r[2]), "=r"(r[3]) : "r"(addr));
}
__device__ __forceinline__ void mma16816(float* c, const uint32_t* a, uint32_t b0, uint32_t b1) {
    asm volatile(
        "mma.sync.aligned.m16n8k16.row.col.f32.f16.f16.f32 "
        "{%0,%1,%2,%3}, {%4,%5,%6,%7}, {%8,%9}, {%0,%1,%2,%3};"
        : "+f"(c[0]), "+f"(c[1]), "+f"(c[2]), "+f"(c[3])
        : "r"(a[0]), "r"(a[1]), "r"(a[2]), "r"(a[3]), "r"(b0), "r"(b1));
}
__device__ __forceinline__ uint32_t pack_h2(float a, float b) {
    __half2 t = __floats2half2_rn(a, b);
    return *reinterpret_cast<uint32_t*>(&t);
}
#define SWZ(o) ((o) ^ (((o) >> 3) & 0x70))

// ---------------- tiny: reset expert counters ----------------
__global__ void reset_cnt() {
    if (threadIdx.x < NEXP) g_cnt[threadIdx.x] = 0;
}

// ================= fused prep kernel =================
__global__ void __launch_bounds__(256)
prep_kernel(const float* __restrict__ x,  const float* __restrict__ Wg,
            const float* __restrict__ bg, const float* __restrict__ W1,
            const float* __restrict__ W2, float* __restrict__ out) {
    const int b = blockIdx.x;
    const int t = threadIdx.x;

    if (b < 512) {
        int tok  = b * 8 + (t >> 5);
        int lane = t & 31;
        const float* xr = x + (size_t)tok * DIM;
        __half* xo = g_x + (size_t)tok * DIM;
        float acc[NEXP];
#pragma unroll
        for (int e = 0; e < NEXP; e++) acc[e] = 0.f;
        for (int d = lane * 2; d < DIM; d += 64) {
            float2 xv = *reinterpret_cast<const float2*>(xr + d);
            *reinterpret_cast<uint32_t*>(xo + d) = pack_h2(xv.x, xv.y);
            const float* wr0 = Wg + d * NEXP;
#pragma unroll
            for (int e = 0; e < NEXP; e++) acc[e] += xv.x * wr0[e];
            const float* wr1 = Wg + (d + 1) * NEXP;
#pragma unroll
            for (int e = 0; e < NEXP; e++) acc[e] += xv.y * wr1[e];
        }
#pragma unroll
        for (int off = 16; off; off >>= 1)
#pragma unroll
            for (int e = 0; e < NEXP; e++)
                acc[e] += __shfl_xor_sync(0xffffffffu, acc[e], off);
        if (lane == 0) {
            float logit[NEXP], m = -1e30f;
#pragma unroll
            for (int e = 0; e < NEXP; e++) { logit[e] = acc[e] + bg[e]; m = fmaxf(m, logit[e]); }
            float p[NEXP], s = 0.f;
#pragma unroll
            for (int e = 0; e < NEXP; e++) { p[e] = expf(logit[e] - m); s += p[e]; }
            float inv = 1.f / s;
#pragma unroll
            for (int e = 0; e < NEXP; e++) p[e] *= inv;
            int e0 = 0;
#pragma unroll
            for (int e = 1; e < NEXP; e++) if (p[e] > p[e0]) e0 = e;
            int e1 = (e0 == 0) ? 1 : 0;
#pragma unroll
            for (int e = 0; e < NEXP; e++) if (e != e0 && p[e] > p[e1]) e1 = e;
            g_wgt[2 * tok + 0] = p[e0];
            g_wgt[2 * tok + 1] = p[e1];
            int p0 = atomicAdd(&g_cnt[e0], 1); g_list[e0][p0] = 2 * tok + 0;
            int p1 = atomicAdd(&g_cnt[e1], 1); g_list[e1][p1] = 2 * tok + 1;
        }
    } else if (b < 33280) {
        const bool isW1 = b < 16896;
        const float* src = isW1 ? W1 : W2;
        __half* dst = isW1 ? g_w1 : g_w2;
        size_t i = ((size_t)(b - (isW1 ? 512 : 16896)) * 256 + t) * 8;
        float v[8];
        *reinterpret_cast<float4*>(v)     = *reinterpret_cast<const float4*>(src + i);
        *reinterpret_cast<float4*>(v + 4) = *reinterpret_cast<const float4*>(src + i + 4);
        uint32_t p[4];
#pragma unroll
        for (int j = 0; j < 4; j++) p[j] = pack_h2(v[2 * j], v[2 * j + 1]);
        *reinterpret_cast<uint4*>(dst + i) = make_uint4(p[0], p[1], p[2], p[3]);
    } else {
        size_t i = ((size_t)(b - 33280) * 256 + t) * 4;
        *reinterpret_cast<float4*>(out + i) = make_float4(0.f, 0.f, 0.f, 0.f);
    }
}

// ------- phase1: 128x128 CTA, K-chunk 128, 64KB stages, 2 CTAs/SM (R12) -------
__global__ void __launch_bounds__(256, 2)
moe_gemm1(const float* __restrict__ bias) {
    constexpr int KD  = DIM;    // 1024
    constexpr int ND  = HID;    // 4096
    constexpr int NCH = KD / 128;
    constexpr int STG = 64 * 1024;

    const __half* A = g_x;
    const __half* B = g_w1;

    const int e   = blockIdx.z;
    const int cnt = g_cnt[e];
    const int m0  = blockIdx.y * 128;
    if (m0 >= cnt) return;
    const int n0  = blockIdx.x * 128;
    const int tid = threadIdx.x;

    extern __shared__ char smraw[];
    char* tilep = (char*)(((uintptr_t)smraw + 1023) & ~(uintptr_t)1023);
    const uint32_t sbase = smem_u32(tilep);
    __shared__ float s_bias[128];
    if (tid < 128) s_bias[tid] = bias[(size_t)e * ND + n0 + tid];

    const int seg = tid & 7;
    const int rg  = tid >> 3;
    uint32_t aoff[4], avalid[4], swza[4];
#pragma unroll
    for (int p = 0; p < 4; p++) {
        int r   = rg + 32 * p;
        int idx = m0 + r;
        int a   = (idx < cnt) ? g_list[e][idx] : 0;
        avalid[p] = (idx < cnt) ? 16u : 0u;
        aoff[p]   = (uint32_t)(a >> 1) * KD + seg * 8;
        swza[p]   = SWZ(r * 128 + seg * 16);
    }
    const int bs  = tid & 15;
    const int brg = tid >> 4;
    uint32_t boff[8], swzb[8];
#pragma unroll
    for (int p = 0; p < 8; p++) {
        int kr  = brg + 16 * p;
        boff[p] = ((uint32_t)e * KD + kr) * ND + n0 + bs * 8;
        swzb[p] = (bs >> 3) * 16384 + SWZ(kr * 128 + (bs & 7) * 16);
    }

    const int lane = tid & 31;
    const int wid  = tid >> 5;
    const int wm   = wid >> 1;
    const int wn   = wid & 1;
    uint32_t abase[2], axor[2];
#pragma unroll
    for (int mf = 0; mf < 2; mf++) {
        int row   = wm * 32 + mf * 16 + (lane & 15);
        abase[mf] = row * 128 + (lane >> 4) * 16;
        axor[mf]  = (row & 7) << 4;
    }
    uint32_t bfr[4];
#pragma unroll
    for (int p = 0; p < 4; p++)
        bfr[p] = (lane & 15) * 128 +
                 ((((uint32_t)(2 * p + (lane >> 4))) * 16) ^ ((lane & 7) << 4));
    const uint32_t bhalf = wn * 16384;

    float acc[2][8][4];
#pragma unroll
    for (int i = 0; i < 2; i++)
#pragma unroll
        for (int j = 0; j < 8; j++)
#pragma unroll
            for (int q = 0; q < 4; q++) acc[i][j][q] = 0.f;

#define ISSUE_CHUNK1(CC, BUF) do {                                             \
        const uint32_t _koA = (uint32_t)(CC) * 128;                            \
        const uint32_t _koB = (uint32_t)(CC) * 128 * ND;                       \
        uint32_t _sb = sbase + (BUF) * STG;                                    \
        _Pragma("unroll")                                                      \
        for (int s = 0; s < 2; s++)                                            \
            _Pragma("unroll")                                                  \
            for (int p = 0; p < 4; p++)                                        \
                cp16(_sb + s * 16384 + swza[p],                                \
                     A + aoff[p] + _koA + s * 64, avalid[p]);                  \
        _Pragma("unroll")                                                      \
        for (int p = 0; p < 8; p++)                                            \
            cp16(_sb + 32768 + swzb[p], B + boff[p] + _koB, 16u);              \
        CP_COMMIT();                                                           \
    } while (0)

    ISSUE_CHUNK1(0, 0);

    for (int c = 0; c < NCH; ++c) {
        if (c + 1 < NCH) {
            ISSUE_CHUNK1(c + 1, (c + 1) & 1);
            CP_WAIT(1);
        } else {
            CP_WAIT(0);
        }
        __syncthreads();

        const uint32_t sb = sbase + (c & 1) * STG;
        const uint32_t bb_base = sb + 32768 + bhalf;
#pragma unroll
        for (int kk = 0; kk < 8; kk++) {
            const uint32_t subA = (kk >> 2) * 16384;
            const uint32_t k4   = (kk & 3) * 32;
            uint32_t ah[2][4], bb[4][4];
#pragma unroll
            for (int mf = 0; mf < 2; mf++)
                ldsm4(ah[mf], sb + subA + ((abase[mf] + k4) ^ axor[mf]));
#pragma unroll
            for (int p = 0; p < 4; p++)
                ldsm4t(bb[p], bb_base + kk * 2048 + bfr[p]);
#pragma unroll
            for (int mf = 0; mf < 2; mf++)
#pragma unroll
                for (int p = 0; p < 4; p++) {
                    mma16816(acc[mf][2 * p],     ah[mf], bb[p][0], bb[p][1]);
                    mma16816(acc[mf][2 * p + 1], ah[mf], bb[p][2], bb[p][3]);
                }
        }
        __syncthreads();
    }
#undef ISSUE_CHUNK1

    const int quad  = lane >> 2;
    const int qid   = lane & 3;
    const int ncol0 = wn * 64;

#pragma unroll
    for (int mf = 0; mf < 2; mf++) {
#pragma unroll
        for (int rv = 0; rv < 2; rv++) {
            int midx = m0 + wm * 32 + mf * 16 + rv * 8 + quad;
            if (midx >= cnt) continue;
            int a = g_list[e][midx];
            __half* dh = g_h + (size_t)a * HID + n0;
#pragma unroll
            for (int nf = 0; nf < 8; nf++) {
                int nloc = ncol0 + nf * 8 + 2 * qid;
                float v0 = fmaxf(acc[mf][nf][2 * rv]     + s_bias[nloc],     0.f);
                float v1 = fmaxf(acc[mf][nf][2 * rv + 1] + s_bias[nloc + 1], 0.f);
                *reinterpret_cast<uint32_t*>(dh + nloc) = pack_h2(v0, v1);
            }
        }
    }
}

// ------- phase2: 128x64 CTA, warp tile 32x32, K-chunk 128, 48KB stages, 2 CTAs/SM -------
// mma:ldsm ratio 2.0 (vs 1.33 at 64x64) to relieve the measured L1 bottleneck (81.7%).
// A-side cloned from gemm1 (128 gathered rows, 2 m-frags, two 16KB k-sub-buffers);
// B-side cloned from the proven 64-wide gemm2 layout.
__global__ void __launch_bounds__(256, 2)
moe_gemm2(const float* __restrict__ bias, float* __restrict__ out) {
    constexpr int KD  = HID;    // 4096
    constexpr int ND  = DIM;    // 1024
    constexpr int NCH = KD / 128;    // 32
    constexpr int STG = 48 * 1024;   // [A0 16K][A1 16K][B 16K]

    const __half* A = g_h;
    const __half* B = g_w2;

    const int e   = blockIdx.z;
    const int cnt = g_cnt[e];
    const int m0  = blockIdx.y * 128;
    if (m0 >= cnt) return;
    const int n0  = blockIdx.x * 64;
    const int tid = threadIdx.x;

    extern __shared__ char smraw[];
    char* tilep = (char*)(((uintptr_t)smraw + 1023) & ~(uintptr_t)1023);
    const uint32_t sbase = smem_u32(tilep);
    __shared__ float s_bias[64];
    if (tid < 64) s_bias[tid] = bias[(size_t)e * ND + n0 + tid];

    // ---- A loads: 128 gathered rows x 128k (two 64-k sub-buffers of 128B rows) ----
    const int seg = tid & 7;
    const int rg  = tid >> 3;
    uint32_t aoff[4], avalid[4], swza[4];
#pragma unroll
    for (int p = 0; p < 4; p++) {
        int r   = rg + 32 * p;
        int idx = m0 + r;
        int a   = (idx < cnt) ? g_list[e][idx] : 0;
        avalid[p] = (idx < cnt) ? 16u : 0u;
        aoff[p]   = (uint32_t)a * KD + seg * 8;
        swza[p]   = SWZ(r * 128 + seg * 16);
    }
    // ---- B loads: 128 k-rows x 64n (128B rows) ----
    uint32_t boff[4], swzb[4];
#pragma unroll
    for (int p = 0; p < 4; p++) {
        int kr  = rg + 32 * p;
        boff[p] = ((uint32_t)e * KD + kr) * ND + n0 + seg * 8;
        swzb[p] = SWZ(kr * 128 + seg * 16);
    }

    const int lane = tid & 31;
    const int wid  = tid >> 5;
    const int wm   = wid >> 1;       // 0..3, m offset wm*32
    const int wn   = wid & 1;        // 0..1, n offset wn*32
    uint32_t abase[2], axor[2];
#pragma unroll
    for (int mf = 0; mf < 2; mf++) {
        int row   = wm * 32 + mf * 16 + (lane & 15);
        abase[mf] = row * 128 + (lane >> 4) * 16;
        axor[mf]  = (row & 7) << 4;
    }
    uint32_t bfr[2];
#pragma unroll
    for (int p = 0; p < 2; p++)
        bfr[p] = (lane & 15) * 128 +
                 ((((uint32_t)(4 * wn + 2 * p + (lane >> 4))) * 16) ^ ((lane & 7) << 4));

    float acc[2][4][4];
#pragma unroll
    for (int i = 0; i < 2; i++)
#pragma unroll
        for (int j = 0; j < 4; j++)
#pragma unroll
            for (int q = 0; q < 4; q++) acc[i][j][q] = 0.f;

#define ISSUE_CHUNK2(CC, BUF) do {                                             \
        const uint32_t _koA = (uint32_t)(CC) * 128;                            \
        const uint32_t _koB = (uint32_t)(CC) * 128 * ND;                       \
        uint32_t _sb = sbase + (BUF) * STG;                                    \
        _Pragma("unroll")                                                      \
        for (int s = 0; s < 2; s++)                                            \
            _Pragma("unroll")                                                  \
            for (int p = 0; p < 4; p++)                                        \
                cp16(_sb + s * 16384 + swza[p],                                \
                     A + aoff[p] + _koA + s * 64, avalid[p]);                  \
        _Pragma("unroll")                                                      \
        for (int p = 0; p < 4; p++)                                            \
            cp16(_sb + 32768 + swzb[p], B + boff[p] + _koB, 16u);              \
        CP_COMMIT();                                                           \
    } while (0)

    ISSUE_CHUNK2(0, 0);

    for (int c = 0; c < NCH; ++c) {
        if (c + 1 < NCH) {
            ISSUE_CHUNK2(c + 1, (c + 1) & 1);
            CP_WAIT(1);
        } else {
            CP_WAIT(0);
        }
        __syncthreads();

        const uint32_t sb = sbase + (c & 1) * STG;
        const uint32_t bb_base = sb + 32768;
#pragma unroll
        for (int kk = 0; kk < 8; kk++) {
            const uint32_t subA = (kk >> 2) * 16384;
            const uint32_t k4   = (kk & 3) * 32;
            uint32_t ah[2][4], bb[2][4];
#pragma unroll
            for (int mf = 0; mf < 2; mf++)
                ldsm4(ah[mf], sb + subA + ((abase[mf] + k4) ^ axor[mf]));
#pragma unroll
            for (int p = 0; p < 2; p++)
                ldsm4t(bb[p], bb_base + kk * 2048 + bfr[p]);
#pragma unroll
            for (int mf = 0; mf < 2; mf++)
#pragma unroll
                for (int p = 0; p < 2; p++) {
                    mma16816(acc[mf][2 * p],     ah[mf], bb[p][0], bb[p][1]);
                    mma16816(acc[mf][2 * p + 1], ah[mf], bb[p][2], bb[p][3]);
                }
        }
        __syncthreads();
    }
#undef ISSUE_CHUNK2

    const int quad  = lane >> 2;
    const int qid   = lane & 3;
    const int ncol0 = wn * 32;

#pragma unroll
    for (int mf = 0; mf < 2; mf++) {
#pragma unroll
        for (int rv = 0; rv < 2; rv++) {
            int midx = m0 + wm * 32 + mf * 16 + rv * 8 + quad;
            if (midx >= cnt) continue;
            int a = g_list[e][midx];
            float w = g_wgt[a];
            float* op = out + (size_t)(a >> 1) * DIM + n0;
#pragma unroll
            for (int nf = 0; nf < 4; nf++) {
                int nloc = ncol0 + nf * 8 + 2 * qid;
                atomicAdd(op + nloc,     (acc[mf][nf][2 * rv]     + s_bias[nloc])     * w);
                atomicAdd(op + nloc + 1, (acc[mf][nf][2 * rv + 1] + s_bias[nloc + 1]) * w);
            }
        }
    }
}

// ---------------- launch (sequential) ----------------
extern "C" void kernel_launch(void* const* d_in, const int* in_sizes, int n_in,
                              void* d_out, int out_size) {
    const float* x  = (const float*)d_in[0];
    const float* Wg = (const float*)d_in[1];
    const float* bg = (const float*)d_in[2];
    const float* W1 = (const float*)d_in[3];
    const float* b1 = (const float*)d_in[4];
    const float* W2 = (const float*)d_in[5];
    const float* b2 = (const float*)d_in[6];
    float* out = (float*)d_out;

    const int SMEM1 = 2 * 64 * 1024 + 1024;
    const int SMEM2 = 2 * 48 * 1024 + 1024;
    cudaFuncSetAttribute((const void*)moe_gemm1,
                         cudaFuncAttributeMaxDynamicSharedMemorySize, SMEM1);
    cudaFuncSetAttribute((const void*)moe_gemm2,
                         cudaFuncAttributeMaxDynamicSharedMemorySize, SMEM2);

    reset_cnt<<<1, 32>>>();
    prep_kernel<<<37376, 256>>>(x, Wg, bg, W1, W2, out);
    moe_gemm1<<<dim3(HID / 128, MAXA / 128, NEXP), 256, SMEM1>>>(b1);
    moe_gemm2<<<dim3(DIM / 64, MAXA / 128, NEXP), 256, SMEM2>>>(b2, out);
}